// round 13
// baseline (speedup 1.0000x reference)
#include <cuda_runtime.h>
#include <cstdint>

#define B_SZ  2
#define GQ    32
#define HDIM  128
#define NH    8
#define DK    16
#define SLEN  4096
#define STILE 8
#define NT    256

typedef unsigned long long u64;

// SMEM (u64 units), total 14464 u64 = 115712 B -> 2 CTAs/SM:
//  sQ  [0,2048)      u64[(d*4+sp)*32 + g]      Q(h); reads end B2, writes post-B2
//  K0  [2048,4096)   float[f*128 + d*8 + s]    K parity 0
//  K1  [4096,6144)                             K parity 1
//  V0  [6144,8192)                             V parity 0
//  V1  [8192,10240)                            V parity 1
//  eX  [10240,14336) u64[(sp*32+f)*32 + g]     probs (written pre-B3, read pre-B4)
//   xSt overlay [10240,12288) u64[(sp*16+d)*32+g]  x staging (post-B4 -> end of h)
//  sSum [14336,14464) u64[sp*32+g]  softmax totals (red.shared, 2 adds/slot)
#define SQ_U64   0
#define K0_U64   2048
#define K1_U64   4096
#define V0_U64   6144
#define V1_U64   8192
#define EX_U64   10240
#define XST_U64  10240
#define SSUM_U64 14336
#define SM_U64_TOTAL 14464
#define SM_BYTES (SM_U64_TOTAL * 8)   // 115712

// Gmem scratch for head-sum accumulators (L2-resident active set ~19MB/wave).
// Layout per item: u64[(sp*32+f)*32 + g]  (lane=g fast -> 256B/warp coalesced)
#define SCR_ITEM_U64 4096u
#define SCR_ITEMS    1024u
#define SCR_HALF     (SCR_ITEMS * SCR_ITEM_U64)
__device__ u64 g_scr[2ull * SCR_HALF];   // [logits | attn], 64 MB

// ---- packed f32x2 + misc helpers ----
__device__ __forceinline__ u64 pk2(float lo, float hi) {
    u64 r; asm("mov.b64 %0, {%1, %2};" : "=l"(r) : "f"(lo), "f"(hi)); return r;
}
__device__ __forceinline__ void up2(u64 v, float& lo, float& hi) {
    asm("mov.b64 {%0, %1}, %2;" : "=f"(lo), "=f"(hi) : "l"(v));
}
__device__ __forceinline__ u64 fma2(u64 a, u64 b, u64 c) {
    u64 d; asm("fma.rn.f32x2 %0, %1, %2, %3;" : "=l"(d) : "l"(a), "l"(b), "l"(c)); return d;
}
__device__ __forceinline__ u64 add2(u64 a, u64 b) {
    u64 d; asm("add.rn.f32x2 %0, %1, %2;" : "=l"(d) : "l"(a), "l"(b)); return d;
}
__device__ __forceinline__ u64 mul2(u64 a, u64 b) {
    u64 d; asm("mul.rn.f32x2 %0, %1, %2;" : "=l"(d) : "l"(a), "l"(b)); return d;
}
__device__ __forceinline__ float ex2a(float x) {
    float r; asm("ex2.approx.ftz.f32 %0, %1;" : "=f"(r) : "f"(x)); return r;
}
__device__ __forceinline__ float rcpa(float x) {
    float r; asm("rcp.approx.ftz.f32 %0, %1;" : "=f"(r) : "f"(x)); return r;
}
__device__ __forceinline__ void cp_async16(void* dst, const void* src) {
    unsigned sdst = (unsigned)__cvta_generic_to_shared(dst);
    asm volatile("cp.async.cg.shared.global [%0], [%1], 16;" :: "r"(sdst), "l"(src));
}
__device__ __forceinline__ void cp_commit() {
    asm volatile("cp.async.commit_group;" ::: "memory");
}
__device__ __forceinline__ void cp_wait0() {
    asm volatile("cp.async.wait_group 0;" ::: "memory");
}
__device__ __forceinline__ void red_shared_f32(void* p, float v) {
    unsigned sa = (unsigned)__cvta_generic_to_shared(p);
    asm volatile("red.shared.add.f32 [%0], %1;" :: "r"(sa), "f"(v) : "memory");
}

// stage a 32x16x8-float tile (K or V): 1024 16B chunks, 4 per thread (NT=256)
__device__ __forceinline__ void stage_async(float* dst, const float* src0, int t) {
    #pragma unroll
    for (int i = 0; i < 4; ++i) {
        int c = t + NT * i;
        int r = c >> 1;                         // row = g*16 + d
        const float* src = src0 + ((size_t)(r >> 4) * HDIM + (r & 15)) * SLEN + 4 * (c & 1);
        cp_async16(dst + 4 * c, src);
    }
}

__device__ __forceinline__ void load_q_ldg(ulonglong2* qA, ulonglong2* qB,
                                           const float* gq, int lane, int w4) {
    #pragma unroll
    for (int i = 0; i < 4; ++i) {
        int d = w4 + 4 * i;
        const float* src = gq + ((size_t)lane * HDIM + d) * SLEN;
        qA[i] = *(const ulonglong2*)(src);
        qB[i] = *(const ulonglong2*)(src + 4);
    }
}
__device__ __forceinline__ void sts_q(u64* sQ, const ulonglong2* qA, const ulonglong2* qB,
                                      int lane, int w4) {
    #pragma unroll
    for (int i = 0; i < 4; ++i) {
        int d = w4 + 4 * i;
        u64* dst = sQ + (size_t)(d * 4) * 32 + lane;
        dst[0] = qA[i].x; dst[32] = qA[i].y; dst[64] = qB[i].x; dst[96] = qB[i].y;
    }
}

__global__ void __launch_bounds__(NT, 2)
sdpa_group_kernel(const float* __restrict__ q, const float* __restrict__ k,
                  const float* __restrict__ v, float* __restrict__ out)
{
    extern __shared__ u64 sm[];
    u64*   sQ   = sm + SQ_U64;
    u64*   eX   = sm + EX_U64;
    u64*   xSt  = sm + XST_U64;
    u64*   sSum = sm + SSUM_U64;

    const int t    = threadIdx.x;
    const int lane = t & 31;
    const int warp = t >> 5;
    const int g    = lane;
    const int sp   = warp & 3;           // s-pair: s = 2sp, 2sp+1
    const int fh   = warp >> 2;          // f-half: f in [16*fh, 16*fh+16)
    const int f0   = fh * 16;
    const int d0   = fh * 8;             // d-half owned in the x phase
    const int gb   = lane & 7;           // x-phase g-slot: g in {2gb,2gb+1,2gb+16,2gb+17}
    const int db   = lane >> 3;          // x-phase d-slot: d in {d0+db, d0+db+4}
    const int s0   = blockIdx.x * STILE;
    const int b    = blockIdx.y;
    const bool qstager = (t < 128);
    const int w4 = warp & 3;

    const int item = b * (SLEN / STILE) + blockIdx.x;
    u64* scrL = g_scr + (size_t)item * SCR_ITEM_U64;
    u64* scrA = scrL + SCR_HALF;

    const size_t base = (size_t)b * (GQ * HDIM) * SLEN + (size_t)s0;
    const float L2E = 1.4426950408889634f;
    const u64 sc = pk2(0.25f * L2E, 0.25f * L2E);        // dk^-0.5 * log2(e)

    // ---- prologue: stage K(0),V(0); Q(0) -> sQ; zero sSum ----
    stage_async((float*)(sm + K0_U64), k + base, t);
    stage_async((float*)(sm + V0_U64), v + base, t);
    cp_commit();
    ulonglong2 qA[4], qB[4];
    if (qstager) {
        load_q_ldg(qA, qB, q + base, lane, w4);
        sts_q(sQ, qA, qB, lane, w4);
    }
    if (t < 128) sSum[t] = 0ull;

    #pragma unroll 1
    for (int h = 0; h < NH; ++h) {
        const int pi = h & 1;
        const float* sKc = (const float*)(sm + (pi ? K1_U64 : K0_U64));
        const float* sVc = (const float*)(sm + (pi ? V1_U64 : V0_U64));

        cp_wait0();              // K(h), V(h) arrived (prefetched a full h ago)
        __syncthreads();         // B1: tiles + Q(h) visible; sSum zeroed

        // issue K(h+1), V(h+1) into the opposite parity NOW (buffers dead since
        // B2/B4 of h-1, both < B1(h)); consumed at B1(h+1): full-iteration distance
        if (h < NH - 1) {
            stage_async((float*)(sm + (pi ? K0_U64 : K1_U64)),
                        k + base + (size_t)(h + 1) * DK * SLEN, t);
            stage_async((float*)(sm + (pi ? V0_U64 : V1_U64)),
                        v + base + (size_t)(h + 1) * DK * SLEN, t);
            cp_commit();
            if (qstager)
                load_q_ldg(qA, qB, q + base + (size_t)(h + 1) * DK * SLEN, lane, w4);
        }

        // ---- qv = Q[g, :, s-pair] * scale ----
        u64 qv[DK];
        {
            const u64* qp = sQ + sp * 32 + g;
            #pragma unroll
            for (int d = 0; d < DK; ++d) qv[d] = mul2(qp[d * 128], sc);
        }

        // ---- logits for this f-half (log2 domain) ----
        u64 lg[16];
        #pragma unroll
        for (int fi = 0; fi < 16; ++fi) {
            const float* kb = sKc + (f0 + fi) * 128 + 2 * sp;
            u64 a0 = mul2(qv[0], *(const u64*)(kb));
            u64 a1 = mul2(qv[1], *(const u64*)(kb + 8));
            #pragma unroll
            for (int d = 2; d < DK; d += 2) {
                a0 = fma2(qv[d],     *(const u64*)(kb + 8 * d),     a0);
                a1 = fma2(qv[d + 1], *(const u64*)(kb + 8 * d + 8), a1);
            }
            lg[fi] = add2(a0, a1);
        }

        // ---- logits sums -> gmem scratch (h==0 stores; else batched RMW) ----
        {
            u64* Lr = scrL + (size_t)((sp * 32 + f0) * 32 + g);
            if (h == 0) {
                #pragma unroll
                for (int fi = 0; fi < 16; ++fi) Lr[fi * 32] = lg[fi];
            } else {
                #pragma unroll
                for (int hb = 0; hb < 2; ++hb) {
                    u64 c[8];
                    #pragma unroll
                    for (int j = 0; j < 8; ++j) c[j] = Lr[(hb * 8 + j) * 32];
                    #pragma unroll
                    for (int j = 0; j < 8; ++j)
                        Lr[(hb * 8 + j) * 32] = add2(c[j], lg[hb * 8 + j]);
                }
            }
        }

        // ---- exp2 + half-sum via red.shared (exactly 2 adds/slot) ----
        #pragma unroll
        for (int fi = 0; fi < 16; ++fi) {
            float a, bb; up2(lg[fi], a, bb);
            lg[fi] = pk2(ex2a(a), ex2a(bb));
        }
        {
            u64 ss[8];
            #pragma unroll
            for (int i = 0; i < 8; ++i) ss[i] = add2(lg[2 * i], lg[2 * i + 1]);
            #pragma unroll
            for (int i = 0; i < 4; ++i) ss[i] = add2(ss[2 * i], ss[2 * i + 1]);
            u64 psum = add2(add2(ss[0], ss[1]), add2(ss[2], ss[3]));
            float p0, p1; up2(psum, p0, p1);
            float* slot = (float*)(sSum + sp * 32 + g);
            red_shared_f32(slot,     p0);
            red_shared_f32(slot + 1, p1);
        }

        __syncthreads();         // B2: logits done (sQ reads done), sums complete

        if (qstager && h < NH - 1) sts_q(sQ, qA, qB, lane, w4);

        // ---- rn; normalize; post probs to dedicated eX ----
        {
            float sum0, sum1; up2(sSum[sp * 32 + g], sum0, sum1);
            const u64 rn = pk2(rcpa(sum0), rcpa(sum1));
            u64* Er = eX + (sp * 32 + f0) * 32 + g;
            #pragma unroll
            for (int fi = 0; fi < 16; ++fi) {
                lg[fi] = mul2(lg[fi], rn);
                Er[fi * 32] = lg[fi];
            }
        }
        __syncthreads();         // B3: probs posted, sSum reads done

        if (t < 128) sSum[t] = 0ull;    // next writes are after B1(h+1)

        // ---- attn sums -> gmem scratch (overlaps x-phase latency) ----
        {
            u64* Ar = scrA + (size_t)((sp * 32 + f0) * 32 + g);
            if (h == 0) {
                #pragma unroll
                for (int fi = 0; fi < 16; ++fi) Ar[fi * 32] = lg[fi];
            } else {
                #pragma unroll
                for (int hb = 0; hb < 2; ++hb) {
                    u64 c[8];
                    #pragma unroll
                    for (int j = 0; j < 8; ++j) c[j] = Ar[(hb * 8 + j) * 32];
                    #pragma unroll
                    for (int j = 0; j < 8; ++j)
                        Ar[(hb * 8 + j) * 32] = add2(c[j], lg[hb * 8 + j]);
                }
            }
        }

        // ---- x phase (register-tiled, conflict-free):
        //      lane owns d in {d0+db, d0+db+4}, g in {2gb,2gb+1,2gb+16,2gb+17} ----
        u64 xa[4], xb[4];
        {
            const u64* er0 = eX + (sp * 32) * 32 + 2 * gb;       // f stride 32 u64
            const float* vf0 = sVc + (d0 + db) * 8 + 2 * sp;     // f stride 128 fl
            {
                ulonglong2 pA = *(const ulonglong2*)(er0);
                ulonglong2 pB = *(const ulonglong2*)(er0 + 16);
                u64 va = *(const u64*)(vf0);
                u64 vb = *(const u64*)(vf0 + 32);
                xa[0] = mul2(pA.x, va); xa[1] = mul2(pA.y, va);
                xa[2] = mul2(pB.x, va); xa[3] = mul2(pB.y, va);
                xb[0] = mul2(pA.x, vb); xb[1] = mul2(pA.y, vb);
                xb[2] = mul2(pB.x, vb); xb[3] = mul2(pB.y, vb);
            }
            #pragma unroll
            for (int f = 1; f < GQ; ++f) {
                const u64* er = er0 + f * 32;
                const float* vf = vf0 + f * 128;
                ulonglong2 pA = *(const ulonglong2*)(er);
                ulonglong2 pB = *(const ulonglong2*)(er + 16);
                u64 va = *(const u64*)(vf);
                u64 vb = *(const u64*)(vf + 32);
                xa[0] = fma2(pA.x, va, xa[0]); xa[1] = fma2(pA.y, va, xa[1]);
                xa[2] = fma2(pB.x, va, xa[2]); xa[3] = fma2(pB.y, va, xa[3]);
                xb[0] = fma2(pA.x, vb, xb[0]); xb[1] = fma2(pA.y, vb, xb[1]);
                xb[2] = fma2(pB.x, vb, xb[2]); xb[3] = fma2(pB.y, vb, xb[3]);
            }
        }
        __syncthreads();         // B4: x-FMAs done everywhere (eX dead -> xSt)

        // ---- stage x into xSt [(sp*16+d)*32+g] via STS.128 ----
        {
            u64* ra = xSt + (sp * 16 + d0 + db)     * 32 + 2 * gb;
            u64* rb = xSt + (sp * 16 + d0 + db + 4) * 32 + 2 * gb;
            ulonglong2 w;
            w.x = xa[0]; w.y = xa[1]; *(ulonglong2*)ra = w;
            w.x = xa[2]; w.y = xa[3]; *(ulonglong2*)(ra + 16) = w;
            w.x = xb[0]; w.y = xb[1]; *(ulonglong2*)rb = w;
            w.x = xb[2]; w.y = xb[3]; *(ulonglong2*)(rb + 16) = w;
        }
        __syncthreads();         // B4.5: x staged

        // ---- cooperative coalesced STG: row (g,d) = 32B, 2 lanes per row ----
        #pragma unroll
        for (int i = 0; i < 4; ++i) {
            int u    = t + NT * i;        // 0..1023 units of 16B
            int r    = u >> 1;
            int half = u & 1;
            int dd   = r >> 5;
            int g2   = r & 31;
            u64 lo = xSt[((2 * half)     * 16 + dd) * 32 + g2];
            u64 hi = xSt[((2 * half + 1) * 16 + dd) * 32 + g2];
            float* dst = out + ((size_t)((b * GQ + g2) * HDIM) + (size_t)h * DK + dd) * SLEN
                             + (size_t)s0 + 4 * half;
            ulonglong2 val; val.x = lo; val.y = hi;
            *(ulonglong2*)dst = val;
        }
        // next writes to xSt region are eX posts of h+1 (post-B2(h+1)),
        // and sQ writes already happened post-B2(h): ordering via B1(h+1).
    }

    // ---- epilogue: bounce scratch -> smem (coalesced), then writeout ----
    __syncthreads();
    u64* smL = sm;                 // [0,4096)
    u64* smA = sm + 4096;          // [4096,8192)  (tiles all dead)
    #pragma unroll
    for (int i = 0; i < 8; ++i) {
        int c2 = t + NT * i;       // 0..2047 ulonglong2 units
        ((ulonglong2*)smL)[c2] = ((const ulonglong2*)scrL)[c2];
        ((ulonglong2*)smA)[c2] = ((const ulonglong2*)scrA)[c2];
    }
    __syncthreads();

    const size_t AOFF = (size_t)B_SZ * GQ * HDIM * SLEN;       // 33554432
    const size_t LOFF = AOFF + (size_t)B_SZ * GQ * GQ * SLEN;  // 41943040
    const u64 cA = pk2(0.125f, 0.125f);
    const float lsc = 0.125f / L2E;                            // undo log2-domain
    const u64 cL = pk2(lsc, lsc);
    #pragma unroll
    for (int i = 0; i < 4; ++i) {
        int r  = t + NT * i;      // 0..1023
        int f  = r & 31;
        int gg = r >> 5;
        size_t o = ((size_t)(b * GQ + gg) * GQ + f) * SLEN + (size_t)s0;
        #pragma unroll
        for (int sp2 = 0; sp2 < 4; ++sp2) {
            int idx = (sp2 * 32 + f) * 32 + gg;
            *(u64*)(out + AOFF + o + 2 * sp2) = mul2(smA[idx], cA);
            *(u64*)(out + LOFF + o + 2 * sp2) = mul2(smL[idx], cL);
        }
    }
}

extern "C" void kernel_launch(void* const* d_in, const int* in_sizes, int n_in,
                              void* d_out, int out_size)
{
    const float* q = (const float*)d_in[0];
    const float* k = (const float*)d_in[1];
    const float* v = (const float*)d_in[2];
    float* out = (float*)d_out;

    cudaFuncSetAttribute(sdpa_group_kernel,
                         cudaFuncAttributeMaxDynamicSharedMemorySize, SM_BYTES);

    dim3 grid(SLEN / STILE, B_SZ);
    sdpa_group_kernel<<<grid, NT, SM_BYTES>>>(q, k, v, out);
}

// round 15
// speedup vs baseline: 1.1220x; 1.1220x over previous
#include <cuda_runtime.h>
#include <cstdint>

#define B_SZ  2
#define GQ    32
#define HDIM  128
#define NH    8
#define DK    16
#define SLEN  4096
#define STILE 8
#define NT    256

typedef unsigned long long u64;

// SMEM (u64 units), total 14464 u64 = 115712 B -> 2 CTAs/SM:
//  sQ   [0,2048)      swizzled [row=g*16+d][s:8]; 16B unit u = g*32+d*2+sh,
//                     stored at u ^ ((g&7)<<1); prescaled by dk^-0.5*log2e
//  sK   [2048,4096)   float[f*128 + d*8 + s]      (K tile; dead after B2)
//    eX  = [0,4096)   u64[(sp*32+f)*32 + g]       probs exchange (B2->B4)
//    xSt = [0,2048)   u64[(sp*16+d)*32 + g]       x staging (B4->B5)
//  sV   [4096,6144)   float[f*128 + d*8 + s]      (V tile; dead after B4)
//  sL   [6144,10240)  u64[(sp*32+f)*32 + g]       logits sums over h
//  sA   [10240,14336) same                        attn sums over h
//  sSum [14336,14464) u64[sp*32 + g]              softmax totals (red.shared,
//                     4 adds/slot; zeroed post-B3)
#define SQ_U64   0
#define SK_U64   2048
#define SV_U64   4096
#define SL_U64   6144
#define SA_U64   10240
#define SSUM_U64 14336
#define SM_U64_TOTAL 14464
#define SM_BYTES (SM_U64_TOTAL * 8)   // 115712

// ---- packed f32x2 + misc helpers ----
__device__ __forceinline__ u64 pk2(float lo, float hi) {
    u64 r; asm("mov.b64 %0, {%1, %2};" : "=l"(r) : "f"(lo), "f"(hi)); return r;
}
__device__ __forceinline__ void up2(u64 v, float& lo, float& hi) {
    asm("mov.b64 {%0, %1}, %2;" : "=f"(lo), "=f"(hi) : "l"(v));
}
__device__ __forceinline__ u64 fma2(u64 a, u64 b, u64 c) {
    u64 d; asm("fma.rn.f32x2 %0, %1, %2, %3;" : "=l"(d) : "l"(a), "l"(b), "l"(c)); return d;
}
__device__ __forceinline__ u64 add2(u64 a, u64 b) {
    u64 d; asm("add.rn.f32x2 %0, %1, %2;" : "=l"(d) : "l"(a), "l"(b)); return d;
}
__device__ __forceinline__ u64 mul2(u64 a, u64 b) {
    u64 d; asm("mul.rn.f32x2 %0, %1, %2;" : "=l"(d) : "l"(a), "l"(b)); return d;
}
__device__ __forceinline__ float ex2a(float x) {
    float r; asm("ex2.approx.ftz.f32 %0, %1;" : "=f"(r) : "f"(x)); return r;
}
__device__ __forceinline__ float rcpa(float x) {
    float r; asm("rcp.approx.ftz.f32 %0, %1;" : "=f"(r) : "f"(x)); return r;
}
__device__ __forceinline__ void cp_async16(void* dst, const void* src) {
    unsigned sdst = (unsigned)__cvta_generic_to_shared(dst);
    asm volatile("cp.async.cg.shared.global [%0], [%1], 16;" :: "r"(sdst), "l"(src));
}
__device__ __forceinline__ void cp_commit() {
    asm volatile("cp.async.commit_group;" ::: "memory");
}
__device__ __forceinline__ void cp_wait0() {
    asm volatile("cp.async.wait_group 0;" ::: "memory");
}
__device__ __forceinline__ void red_shared_f32(void* p, float v) {
    unsigned sa = (unsigned)__cvta_generic_to_shared(p);
    asm volatile("red.shared.add.f32 [%0], %1;" :: "r"(sa), "f"(v) : "memory");
}

// stage a 32x16x8-float tile (K or V): 1024 16B chunks, 4 per thread (NT=256)
__device__ __forceinline__ void stage_async(float* dst, const float* src0, int t) {
    #pragma unroll
    for (int i = 0; i < 4; ++i) {
        int c = t + NT * i;
        int r = c >> 1;                         // row = g*16 + d
        const float* src = src0 + ((size_t)(r >> 4) * HDIM + (r & 15)) * SLEN + 4 * (c & 1);
        cp_async16(dst + 4 * c, src);
    }
}

// Q: 1024 16B chunks by ALL 256 threads (4 each), coalesced-chunked LDG -> regs
__device__ __forceinline__ void load_q_chunks(ulonglong2* qc, const float* gq, int t) {
    #pragma unroll
    for (int i = 0; i < 4; ++i) {
        int c = t + NT * i;                     // 0..1023, c = (g*16+d)*2 + half
        int r = c >> 1;                         // g = r>>4, d = r&15
        const float* src = gq + ((size_t)(r >> 4) * HDIM + (r & 15)) * SLEN + 4 * (c & 1);
        qc[i] = *(const ulonglong2*)src;
    }
}
// prescaled, swizzled STS: unit u = c; store at u ^ ((g&7)<<1)
__device__ __forceinline__ void sts_q_chunks(u64* sQ, const ulonglong2* qc, int t, u64 sc) {
    #pragma unroll
    for (int i = 0; i < 4; ++i) {
        int c = t + NT * i;                     // 0..1023
        int gg = c >> 5;                        // g = 0..31
        int u  = c ^ ((gg & 7) << 1);
        ulonglong2 v;
        v.x = mul2(qc[i].x, sc);
        v.y = mul2(qc[i].y, sc);
        *(ulonglong2*)(sQ + 2 * u) = v;
    }
}

__global__ void __launch_bounds__(NT, 2)
sdpa_group_kernel(const float* __restrict__ q, const float* __restrict__ k,
                  const float* __restrict__ v, float* __restrict__ out)
{
    extern __shared__ u64 sm[];
    u64*   sQ   = sm + SQ_U64;
    u64*   eX   = sm + SQ_U64;     // overlay, live B2->B4
    u64*   xSt  = sm + SQ_U64;     // overlay, live B4->B5
    float* sK   = (float*)(sm + SK_U64);
    float* sV   = (float*)(sm + SV_U64);
    u64*   sL   = sm + SL_U64;
    u64*   sA   = sm + SA_U64;
    u64*   sSum = sm + SSUM_U64;

    const int t    = threadIdx.x;
    const int g    = t & 31;
    const int warp = t >> 5;
    // logits roles: s-quad x f-octet
    const int sq   = warp & 1;           // s in [4sq, 4sq+4); spins = s-pairs 2sq, 2sq+1
    const int fq   = warp >> 1;          // f in [8fq, 8fq+8)
    const int f0l  = fq * 8;
    // x-phase roles (R12)
    const int sp   = warp & 3;
    const int fh   = warp >> 2;
    const int d0   = fh * 8;
    const int gb   = g & 7;
    const int db   = g >> 3;
    const int s0   = blockIdx.x * STILE;
    const int b    = blockIdx.y;
    const int xorv = (g & 7) << 1;

    const size_t base = (size_t)b * (GQ * HDIM) * SLEN + (size_t)s0;
    const float L2E = 1.4426950408889634f;
    const u64 sc = pk2(0.25f * L2E, 0.25f * L2E);        // dk^-0.5 * log2(e)

    // ---- prologue ----
    stage_async(sK, k + base, t);
    stage_async(sV, v + base, t);
    cp_commit();
    ulonglong2 qc[4];
    load_q_chunks(qc, q + base, t);
    #pragma unroll 4
    for (int i = t; i < 8320; i += NT) sL[i] = 0ull;     // sL,sA,sSum contiguous
    sts_q_chunks(sQ, qc, t, sc);

    #pragma unroll 1
    for (int h = 0; h < NH; ++h) {
        cp_wait0();              // K(h), V(h) arrived
        __syncthreads();         // B1: tiles + Q(h) visible

        if (h < NH - 1)
            load_q_chunks(qc, q + base + (size_t)(h + 1) * DK * SLEN, t);

        // ---- logits: (8 f) x (4 s) per warp, log2 domain, 2 d-passes ----
        u64 lg0[8], lg1[8];      // [fi] for spins 2sq, 2sq+1
        const u64* qrow = sQ + g * 64;     // unit base g*32, 2 u64/unit
        #pragma unroll
        for (int pass = 0; pass < 2; ++pass) {
            ulonglong2 qvh[8];
            #pragma unroll
            for (int dd = 0; dd < 8; ++dd) {
                int u = (((pass * 8 + dd) * 2 + sq) ^ xorv);
                qvh[dd] = *(const ulonglong2*)(qrow + 2 * u);
            }
            #pragma unroll
            for (int fi = 0; fi < 8; ++fi) {
                const float* kb = sK + (f0l + fi) * 128 + pass * 64 + 4 * sq;
                #pragma unroll
                for (int dd = 0; dd < 8; ++dd) {
                    ulonglong2 kk = *(const ulonglong2*)(kb + dd * 8);
                    if (pass == 0 && dd == 0) {
                        lg0[fi] = mul2(qvh[0].x, kk.x);
                        lg1[fi] = mul2(qvh[0].y, kk.y);
                    } else {
                        lg0[fi] = fma2(qvh[dd].x, kk.x, lg0[fi]);
                        lg1[fi] = fma2(qvh[dd].y, kk.y, lg1[fi]);
                    }
                }
            }
        }

        // ---- accumulate logits sums ----
        {
            u64* Lr0 = sL + ((2 * sq)     * 32 + f0l) * 32 + g;
            u64* Lr1 = sL + ((2 * sq + 1) * 32 + f0l) * 32 + g;
            #pragma unroll
            for (int fi = 0; fi < 8; ++fi) {
                Lr0[fi * 32] = add2(Lr0[fi * 32], lg0[fi]);
                Lr1[fi * 32] = add2(Lr1[fi * 32], lg1[fi]);
            }
        }

        // ---- exp2 + octet partial sums via red.shared (4 adds/slot) ----
        #pragma unroll
        for (int fi = 0; fi < 8; ++fi) {
            float a, bb;
            up2(lg0[fi], a, bb); lg0[fi] = pk2(ex2a(a), ex2a(bb));
            up2(lg1[fi], a, bb); lg1[fi] = pk2(ex2a(a), ex2a(bb));
        }
        {
            u64 p0 = add2(add2(add2(lg0[0], lg0[1]), add2(lg0[2], lg0[3])),
                          add2(add2(lg0[4], lg0[5]), add2(lg0[6], lg0[7])));
            u64 p1 = add2(add2(add2(lg1[0], lg1[1]), add2(lg1[2], lg1[3])),
                          add2(add2(lg1[4], lg1[5]), add2(lg1[6], lg1[7])));
            float a, bb;
            float* s0f = (float*)(sSum + (2 * sq) * 32 + g);
            up2(p0, a, bb); red_shared_f32(s0f, a); red_shared_f32(s0f + 1, bb);
            float* s1f = (float*)(sSum + (2 * sq + 1) * 32 + g);
            up2(p1, a, bb); red_shared_f32(s1f, a); red_shared_f32(s1f + 1, bb);
        }

        __syncthreads();         // B2: logits done (sQ, sK dead), sums complete

        // ---- rn; normalize; accumulate attn sums; post probs to eX ----
        {
            float u0, u1;
            up2(sSum[(2 * sq) * 32 + g], u0, u1);
            const u64 rn0 = pk2(rcpa(u0), rcpa(u1));
            up2(sSum[(2 * sq + 1) * 32 + g], u0, u1);
            const u64 rn1 = pk2(rcpa(u0), rcpa(u1));
            u64* Ar0 = sA + ((2 * sq)     * 32 + f0l) * 32 + g;
            u64* Ar1 = sA + ((2 * sq + 1) * 32 + f0l) * 32 + g;
            u64* Er0 = eX + ((2 * sq)     * 32 + f0l) * 32 + g;
            u64* Er1 = eX + ((2 * sq + 1) * 32 + f0l) * 32 + g;
            #pragma unroll
            for (int fi = 0; fi < 8; ++fi) {
                lg0[fi] = mul2(lg0[fi], rn0);
                lg1[fi] = mul2(lg1[fi], rn1);
                Ar0[fi * 32] = add2(Ar0[fi * 32], lg0[fi]);
                Ar1[fi * 32] = add2(Ar1[fi * 32], lg1[fi]);
                Er0[fi * 32] = lg0[fi];
                Er1[fi * 32] = lg1[fi];
            }
        }
        __syncthreads();         // B3: probs posted, sSum reads done

        if (t < 128) sSum[t] = 0ull;   // next adds after B1(h+1)

        // ---- x phase (register-tiled, conflict-free; R12):
        //      lane owns d in {d0+db, d0+db+4}, g in {2gb,2gb+1,2gb+16,2gb+17} ----
        u64 xa[4], xb[4];
        {
            const u64* er0 = eX + (sp * 32) * 32 + 2 * gb;       // f stride 32 u64
            const float* vf0 = sV + (d0 + db) * 8 + 2 * sp;      // f stride 128 fl
            {
                ulonglong2 pA = *(const ulonglong2*)(er0);
                ulonglong2 pB = *(const ulonglong2*)(er0 + 16);
                u64 va = *(const u64*)(vf0);
                u64 vb = *(const u64*)(vf0 + 32);
                xa[0] = mul2(pA.x, va); xa[1] = mul2(pA.y, va);
                xa[2] = mul2(pB.x, va); xa[3] = mul2(pB.y, va);
                xb[0] = mul2(pA.x, vb); xb[1] = mul2(pA.y, vb);
                xb[2] = mul2(pB.x, vb); xb[3] = mul2(pB.y, vb);
            }
            #pragma unroll
            for (int f = 1; f < GQ; ++f) {
                const u64* er = er0 + f * 32;
                const float* vf = vf0 + f * 128;
                ulonglong2 pA = *(const ulonglong2*)(er);
                ulonglong2 pB = *(const ulonglong2*)(er + 16);
                u64 va = *(const u64*)(vf);
                u64 vb = *(const u64*)(vf + 32);
                xa[0] = fma2(pA.x, va, xa[0]); xa[1] = fma2(pA.y, va, xa[1]);
                xa[2] = fma2(pB.x, va, xa[2]); xa[3] = fma2(pB.y, va, xa[3]);
                xb[0] = fma2(pA.x, vb, xb[0]); xb[1] = fma2(pA.y, vb, xb[1]);
                xb[2] = fma2(pB.x, vb, xb[2]); xb[3] = fma2(pB.y, vb, xb[3]);
            }
        }
        __syncthreads();         // B4: x-FMAs done everywhere (eX, sV, sK dead)

        // prefetch K(h+1), V(h+1)
        if (h < NH - 1) {
            stage_async(sK, k + base + (size_t)(h + 1) * DK * SLEN, t);
            stage_async(sV, v + base + (size_t)(h + 1) * DK * SLEN, t);
            cp_commit();
        }

        // ---- stage x into xSt [(sp*16+d)*32+g] via STS.128 ----
        {
            u64* ra = xSt + (sp * 16 + d0 + db)     * 32 + 2 * gb;
            u64* rb = xSt + (sp * 16 + d0 + db + 4) * 32 + 2 * gb;
            ulonglong2 w;
            w.x = xa[0]; w.y = xa[1]; *(ulonglong2*)ra = w;
            w.x = xa[2]; w.y = xa[3]; *(ulonglong2*)(ra + 16) = w;
            w.x = xb[0]; w.y = xb[1]; *(ulonglong2*)rb = w;
            w.x = xb[2]; w.y = xb[3]; *(ulonglong2*)(rb + 16) = w;
        }
        __syncthreads();         // B4.5: x staged

        // ---- cooperative coalesced STG: row (g,d) = 32B, 2 lanes per row ----
        #pragma unroll
        for (int i = 0; i < 4; ++i) {
            int u    = t + NT * i;        // 0..1023 units of 16B
            int r    = u >> 1;
            int half = u & 1;
            int dd   = r >> 5;
            int g2   = r & 31;
            u64 lo = xSt[((2 * half)     * 16 + dd) * 32 + g2];
            u64 hi = xSt[((2 * half + 1) * 16 + dd) * 32 + g2];
            float* dst = out + ((size_t)((b * GQ + g2) * HDIM) + (size_t)h * DK + dd) * SLEN
                             + (size_t)s0 + 4 * half;
            ulonglong2 val; val.x = lo; val.y = hi;
            *(ulonglong2*)dst = val;
        }
        __syncthreads();         // B5: staging reads done -> region free for Q(h+1)

        if (h < NH - 1) sts_q_chunks(sQ, qc, t, sc);
    }

    // ---- writeout head means ----
    __syncthreads();
    const size_t AOFF = (size_t)B_SZ * GQ * HDIM * SLEN;       // 33554432
    const size_t LOFF = AOFF + (size_t)B_SZ * GQ * GQ * SLEN;  // 41943040
    const u64 cA = pk2(0.125f, 0.125f);
    const float lsc = 0.125f / L2E;                            // undo log2-domain
    const u64 cL = pk2(lsc, lsc);
    #pragma unroll
    for (int i = 0; i < 4; ++i) {
        int r  = t + NT * i;      // 0..1023
        int f  = r & 31;
        int gg = r >> 5;
        size_t o = ((size_t)(b * GQ + gg) * GQ + f) * SLEN + (size_t)s0;
        #pragma unroll
        for (int sp2 = 0; sp2 < 4; ++sp2) {
            int idx = (sp2 * 32 + f) * 32 + gg;
            *(u64*)(out + AOFF + o + 2 * sp2) = mul2(sA[idx], cA);
            *(u64*)(out + LOFF + o + 2 * sp2) = mul2(sL[idx], cL);
        }
    }
}

extern "C" void kernel_launch(void* const* d_in, const int* in_sizes, int n_in,
                              void* d_out, int out_size)
{
    const float* q = (const float*)d_in[0];
    const float* k = (const float*)d_in[1];
    const float* v = (const float*)d_in[2];
    float* out = (float*)d_out;

    cudaFuncSetAttribute(sdpa_group_kernel,
                         cudaFuncAttributeMaxDynamicSharedMemorySize, SM_BYTES);

    dim3 grid(SLEN / STILE, B_SZ);
    sdpa_group_kernel<<<grid, NT, SM_BYTES>>>(q, k, v, out);
}

// round 16
// speedup vs baseline: 1.1384x; 1.0147x over previous
#include <cuda_runtime.h>
#include <cstdint>

#define B_SZ  2
#define GQ    32
#define HDIM  128
#define NH    8
#define DK    16
#define SLEN  4096
#define STILE 8
#define NT    256

typedef unsigned long long u64;

// SMEM (u64 units), total 14464 u64 = 115712 B -> 2 CTAs/SM:
//  sQ   [0,2048)      [row=g*16+d][s:8]; 16B unit u = g*32+d*2+sh stored at
//                     g*32 + ((d*2+sh) ^ (g&7)); prescaled by dk^-0.5*log2e
//  sK   [2048,4096)   float[f*128 + d*8 + s]      (K tile; dead after B2)
//    eX  = [0,4096)   u64[(sp*32+f)*32 + g]       probs exchange (B2->B4)
//    xSt = [0,2048)   u64[(sp*16+d)*32 + g]       x staging (B4->B5)
//  sV   [4096,6144)   float[f*128 + d*8 + s]      (V tile; dead after B4)
//  sL   [6144,10240)  u64[(sp*32+f)*32 + g]       logits sums over h
//  sA   [10240,14336) same                        attn sums over h
//  sSum [14336,14464) u64[sp*32 + g]              softmax totals (red.shared,
//                     4 adds/slot; zeroed post-B3)
#define SQ_U64   0
#define SK_U64   2048
#define SV_U64   4096
#define SL_U64   6144
#define SA_U64   10240
#define SSUM_U64 14336
#define SM_U64_TOTAL 14464
#define SM_BYTES (SM_U64_TOTAL * 8)   // 115712

// ---- packed f32x2 + misc helpers ----
__device__ __forceinline__ u64 pk2(float lo, float hi) {
    u64 r; asm("mov.b64 %0, {%1, %2};" : "=l"(r) : "f"(lo), "f"(hi)); return r;
}
__device__ __forceinline__ void up2(u64 v, float& lo, float& hi) {
    asm("mov.b64 {%0, %1}, %2;" : "=f"(lo), "=f"(hi) : "l"(v));
}
__device__ __forceinline__ u64 fma2(u64 a, u64 b, u64 c) {
    u64 d; asm("fma.rn.f32x2 %0, %1, %2, %3;" : "=l"(d) : "l"(a), "l"(b), "l"(c)); return d;
}
__device__ __forceinline__ u64 add2(u64 a, u64 b) {
    u64 d; asm("add.rn.f32x2 %0, %1, %2;" : "=l"(d) : "l"(a), "l"(b)); return d;
}
__device__ __forceinline__ u64 mul2(u64 a, u64 b) {
    u64 d; asm("mul.rn.f32x2 %0, %1, %2;" : "=l"(d) : "l"(a), "l"(b)); return d;
}
__device__ __forceinline__ float ex2a(float x) {
    float r; asm("ex2.approx.ftz.f32 %0, %1;" : "=f"(r) : "f"(x)); return r;
}
__device__ __forceinline__ float rcpa(float x) {
    float r; asm("rcp.approx.ftz.f32 %0, %1;" : "=f"(r) : "f"(x)); return r;
}
__device__ __forceinline__ u64 ex2a2(u64 v) {
    float a, b; up2(v, a, b);
    return pk2(ex2a(a), ex2a(b));
}
__device__ __forceinline__ u64 rcpa2(u64 v) {
    float a, b; up2(v, a, b);
    return pk2(rcpa(a), rcpa(b));
}
__device__ __forceinline__ void cp_async16(void* dst, const void* src) {
    unsigned sdst = (unsigned)__cvta_generic_to_shared(dst);
    asm volatile("cp.async.cg.shared.global [%0], [%1], 16;" :: "r"(sdst), "l"(src));
}
__device__ __forceinline__ void cp_commit() {
    asm volatile("cp.async.commit_group;" ::: "memory");
}
__device__ __forceinline__ void cp_wait0() {
    asm volatile("cp.async.wait_group 0;" ::: "memory");
}
__device__ __forceinline__ void red_shared_f32(void* p, float v) {
    unsigned sa = (unsigned)__cvta_generic_to_shared(p);
    asm volatile("red.shared.add.f32 [%0], %1;" :: "r"(sa), "f"(v) : "memory");
}

// stage a 32x16x8-float tile (K or V): 1024 16B chunks, 4 per thread (NT=256)
__device__ __forceinline__ void stage_async(float* dst, const float* src0, int t) {
    #pragma unroll
    for (int i = 0; i < 4; ++i) {
        int c = t + NT * i;
        int r = c >> 1;                         // row = g*16 + d
        const float* src = src0 + ((size_t)(r >> 4) * HDIM + (r & 15)) * SLEN + 4 * (c & 1);
        cp_async16(dst + 4 * c, src);
    }
}

// Q: 1024 16B chunks by ALL 256 threads (4 each), coalesced-chunked LDG -> regs
__device__ __forceinline__ void load_q_chunks(ulonglong2* qc, const float* gq, int t) {
    #pragma unroll
    for (int i = 0; i < 4; ++i) {
        int c = t + NT * i;                     // 0..1023, c = (g*16+d)*2 + half
        int r = c >> 1;                         // g = r>>4, d = r&15
        const float* src = gq + ((size_t)(r >> 4) * HDIM + (r & 15)) * SLEN + 4 * (c & 1);
        qc[i] = *(const ulonglong2*)src;
    }
}
// prescaled, swizzled STS: unit u = c ^ (g&7)  [xor hits low 3 bits of (d*2+h)]
__device__ __forceinline__ void sts_q_chunks(u64* sQ, const ulonglong2* qc, int t, u64 sc) {
    #pragma unroll
    for (int i = 0; i < 4; ++i) {
        int c = t + NT * i;                     // 0..1023
        int gg = c >> 5;                        // g = 0..31
        int u  = c ^ (gg & 7);
        ulonglong2 v;
        v.x = mul2(qc[i].x, sc);
        v.y = mul2(qc[i].y, sc);
        *(ulonglong2*)(sQ + 2 * u) = v;
    }
}

__global__ void __launch_bounds__(NT, 2)
sdpa_group_kernel(const float* __restrict__ q, const float* __restrict__ k,
                  const float* __restrict__ v, float* __restrict__ out)
{
    extern __shared__ u64 sm[];
    u64*   sQ   = sm + SQ_U64;
    u64*   eX   = sm + SQ_U64;     // overlay, live B2->B4
    u64*   xSt  = sm + SQ_U64;     // overlay, live B4->B5
    float* sK   = (float*)(sm + SK_U64);
    float* sV   = (float*)(sm + SV_U64);
    u64*   sL   = sm + SL_U64;
    u64*   sA   = sm + SA_U64;
    u64*   sSum = sm + SSUM_U64;

    const int t    = threadIdx.x;
    const int g    = t & 31;
    const int warp = t >> 5;
    // logits roles: warp (sq, fq); lane (gh, fb)
    const int sq   = warp & 1;           // s-quad: spins (s-pairs) 2sq, 2sq+1
    const int fq   = warp >> 1;          // f-octet: f in [8fq, 8fq+8)
    const int f0l  = fq * 8;
    const int gh   = g & 15;             // owns g in {gh, gh+16}
    const int fb   = g >> 4;             // owns f in [f0l+4fb, f0l+4fb+4)
    const int fL   = f0l + 4 * fb;
    // x-phase roles (R12)
    const int sp   = warp & 3;
    const int fh   = warp >> 2;
    const int d0   = fh * 8;
    const int gb   = g & 7;
    const int db   = g >> 3;
    const int s0   = blockIdx.x * STILE;
    const int b    = blockIdx.y;

    const size_t base = (size_t)b * (GQ * HDIM) * SLEN + (size_t)s0;
    const float L2E = 1.4426950408889634f;
    const u64 sc = pk2(0.25f * L2E, 0.25f * L2E);        // dk^-0.5 * log2(e)

    // ---- prologue ----
    stage_async(sK, k + base, t);
    stage_async(sV, v + base, t);
    cp_commit();
    ulonglong2 qc[4];
    load_q_chunks(qc, q + base, t);
    #pragma unroll 4
    for (int i = t; i < 8320; i += NT) sL[i] = 0ull;     // sL,sA,sSum contiguous
    sts_q_chunks(sQ, qc, t, sc);

    #pragma unroll 1
    for (int h = 0; h < NH; ++h) {
        cp_wait0();              // K(h), V(h) arrived
        __syncthreads();         // B1: tiles + Q(h) visible

        if (h < NH - 1)
            load_q_chunks(qc, q + base + (size_t)(h + 1) * DK * SLEN, t);

        // ---- logits (register-tiled 2g x 4f, log2 domain) ----
        // lgA*: g = gh, lgB*: g = gh+16; suffix 0/1 = spin 2sq / 2sq+1
        u64 lgA0[4], lgA1[4], lgB0[4], lgB1[4];
        {
            const int xa = gh & 7;                       // same for gh and gh+16
            const u64* qbA = sQ + 2 * (gh * 32);
            const u64* qbB = sQ + 2 * ((gh + 16) * 32);
            const float* kb = sK + fL * 128 + 4 * sq;
            #pragma unroll
            for (int d = 0; d < DK; ++d) {
                const int uo = 2 * ((d * 2 + sq) ^ xa);
                ulonglong2 qa = *(const ulonglong2*)(qbA + uo);
                ulonglong2 qb = *(const ulonglong2*)(qbB + uo);
                #pragma unroll
                for (int j = 0; j < 4; ++j) {
                    ulonglong2 kk = *(const ulonglong2*)(kb + j * 128 + d * 8);
                    if (d == 0) {
                        lgA0[j] = mul2(qa.x, kk.x); lgA1[j] = mul2(qa.y, kk.y);
                        lgB0[j] = mul2(qb.x, kk.x); lgB1[j] = mul2(qb.y, kk.y);
                    } else {
                        lgA0[j] = fma2(qa.x, kk.x, lgA0[j]);
                        lgA1[j] = fma2(qa.y, kk.y, lgA1[j]);
                        lgB0[j] = fma2(qb.x, kk.x, lgB0[j]);
                        lgB1[j] = fma2(qb.y, kk.y, lgB1[j]);
                    }
                }
            }
        }

        // ---- accumulate logits sums + exp2 ----
        #pragma unroll
        for (int j = 0; j < 4; ++j) {
            u64* p0 = sL + ((2 * sq)     * 32 + fL + j) * 32 + gh;
            u64* p1 = sL + ((2 * sq + 1) * 32 + fL + j) * 32 + gh;
            p0[0]  = add2(p0[0],  lgA0[j]);
            p0[16] = add2(p0[16], lgB0[j]);
            p1[0]  = add2(p1[0],  lgA1[j]);
            p1[16] = add2(p1[16], lgB1[j]);
            lgA0[j] = ex2a2(lgA0[j]); lgA1[j] = ex2a2(lgA1[j]);
            lgB0[j] = ex2a2(lgB0[j]); lgB1[j] = ex2a2(lgB1[j]);
        }

        // ---- softmax partials: sum 4f, fold fb via shfl, red.shared ----
        {
            u64 pA0 = add2(add2(lgA0[0], lgA0[1]), add2(lgA0[2], lgA0[3]));
            u64 pA1 = add2(add2(lgA1[0], lgA1[1]), add2(lgA1[2], lgA1[3]));
            u64 pB0 = add2(add2(lgB0[0], lgB0[1]), add2(lgB0[2], lgB0[3]));
            u64 pB1 = add2(add2(lgB1[0], lgB1[1]), add2(lgB1[2], lgB1[3]));
            pA0 = add2(pA0, __shfl_xor_sync(0xffffffffu, pA0, 16));
            pA1 = add2(pA1, __shfl_xor_sync(0xffffffffu, pA1, 16));
            pB0 = add2(pB0, __shfl_xor_sync(0xffffffffu, pB0, 16));
            pB1 = add2(pB1, __shfl_xor_sync(0xffffffffu, pB1, 16));
            if (fb == 0) {
                float a, bb;
                float* s00 = (float*)(sSum + (2 * sq) * 32 + gh);
                up2(pA0, a, bb); red_shared_f32(s00, a); red_shared_f32(s00 + 1, bb);
                float* s0B = (float*)(sSum + (2 * sq) * 32 + gh + 16);
                up2(pB0, a, bb); red_shared_f32(s0B, a); red_shared_f32(s0B + 1, bb);
                float* s10 = (float*)(sSum + (2 * sq + 1) * 32 + gh);
                up2(pA1, a, bb); red_shared_f32(s10, a); red_shared_f32(s10 + 1, bb);
                float* s1B = (float*)(sSum + (2 * sq + 1) * 32 + gh + 16);
                up2(pB1, a, bb); red_shared_f32(s1B, a); red_shared_f32(s1B + 1, bb);
            }
        }

        __syncthreads();         // B2: logits done (sQ, sK dead), sums complete

        // ---- rn; normalize; accumulate attn sums; post probs to eX ----
        {
            const u64 rnA0 = rcpa2(sSum[(2 * sq)     * 32 + gh]);
            const u64 rnB0 = rcpa2(sSum[(2 * sq)     * 32 + gh + 16]);
            const u64 rnA1 = rcpa2(sSum[(2 * sq + 1) * 32 + gh]);
            const u64 rnB1 = rcpa2(sSum[(2 * sq + 1) * 32 + gh + 16]);
            #pragma unroll
            for (int j = 0; j < 4; ++j) {
                const int i0 = ((2 * sq)     * 32 + fL + j) * 32 + gh;
                const int i1 = ((2 * sq + 1) * 32 + fL + j) * 32 + gh;
                u64 vA0 = mul2(lgA0[j], rnA0);
                u64 vB0 = mul2(lgB0[j], rnB0);
                u64 vA1 = mul2(lgA1[j], rnA1);
                u64 vB1 = mul2(lgB1[j], rnB1);
                sA[i0]      = add2(sA[i0],      vA0);
                sA[i0 + 16] = add2(sA[i0 + 16], vB0);
                sA[i1]      = add2(sA[i1],      vA1);
                sA[i1 + 16] = add2(sA[i1 + 16], vB1);
                eX[i0]      = vA0;
                eX[i0 + 16] = vB0;
                eX[i1]      = vA1;
                eX[i1 + 16] = vB1;
            }
        }
        __syncthreads();         // B3: probs posted, sSum reads done

        if (t < 128) sSum[t] = 0ull;   // next adds after B1(h+1)

        // ---- x phase (register-tiled, conflict-free; R12):
        //      lane owns d in {d0+db, d0+db+4}, g in {2gb,2gb+1,2gb+16,2gb+17} ----
        u64 xa[4], xb[4];
        {
            const u64* er0 = eX + (sp * 32) * 32 + 2 * gb;       // f stride 32 u64
            const float* vf0 = sV + (d0 + db) * 8 + 2 * sp;      // f stride 128 fl
            {
                ulonglong2 pA = *(const ulonglong2*)(er0);
                ulonglong2 pB = *(const ulonglong2*)(er0 + 16);
                u64 va = *(const u64*)(vf0);
                u64 vb = *(const u64*)(vf0 + 32);
                xa[0] = mul2(pA.x, va); xa[1] = mul2(pA.y, va);
                xa[2] = mul2(pB.x, va); xa[3] = mul2(pB.y, va);
                xb[0] = mul2(pA.x, vb); xb[1] = mul2(pA.y, vb);
                xb[2] = mul2(pB.x, vb); xb[3] = mul2(pB.y, vb);
            }
            #pragma unroll
            for (int f = 1; f < GQ; ++f) {
                const u64* er = er0 + f * 32;
                const float* vf = vf0 + f * 128;
                ulonglong2 pA = *(const ulonglong2*)(er);
                ulonglong2 pB = *(const ulonglong2*)(er + 16);
                u64 va = *(const u64*)(vf);
                u64 vb = *(const u64*)(vf + 32);
                xa[0] = fma2(pA.x, va, xa[0]); xa[1] = fma2(pA.y, va, xa[1]);
                xa[2] = fma2(pB.x, va, xa[2]); xa[3] = fma2(pB.y, va, xa[3]);
                xb[0] = fma2(pA.x, vb, xb[0]); xb[1] = fma2(pA.y, vb, xb[1]);
                xb[2] = fma2(pB.x, vb, xb[2]); xb[3] = fma2(pB.y, vb, xb[3]);
            }
        }
        __syncthreads();         // B4: x-FMAs done everywhere (eX, sV, sK dead)

        // prefetch K(h+1), V(h+1)
        if (h < NH - 1) {
            stage_async(sK, k + base + (size_t)(h + 1) * DK * SLEN, t);
            stage_async(sV, v + base + (size_t)(h + 1) * DK * SLEN, t);
            cp_commit();
        }

        // ---- stage x into xSt [(sp*16+d)*32+g] via STS.128 ----
        {
            u64* ra = xSt + (sp * 16 + d0 + db)     * 32 + 2 * gb;
            u64* rb = xSt + (sp * 16 + d0 + db + 4) * 32 + 2 * gb;
            ulonglong2 w;
            w.x = xa[0]; w.y = xa[1]; *(ulonglong2*)ra = w;
            w.x = xa[2]; w.y = xa[3]; *(ulonglong2*)(ra + 16) = w;
            w.x = xb[0]; w.y = xb[1]; *(ulonglong2*)rb = w;
            w.x = xb[2]; w.y = xb[3]; *(ulonglong2*)(rb + 16) = w;
        }
        __syncthreads();         // B4.5: x staged

        // ---- cooperative coalesced STG: row (g,d) = 32B, 2 lanes per row ----
        #pragma unroll
        for (int i = 0; i < 4; ++i) {
            int u    = t + NT * i;        // 0..1023 units of 16B
            int r    = u >> 1;
            int half = u & 1;
            int dd   = r >> 5;
            int g2   = r & 31;
            u64 lo = xSt[((2 * half)     * 16 + dd) * 32 + g2];
            u64 hi = xSt[((2 * half + 1) * 16 + dd) * 32 + g2];
            float* dst = out + ((size_t)((b * GQ + g2) * HDIM) + (size_t)h * DK + dd) * SLEN
                             + (size_t)s0 + 4 * half;
            ulonglong2 val; val.x = lo; val.y = hi;
            *(ulonglong2*)dst = val;
        }
        __syncthreads();         // B5: staging reads done -> region free for Q(h+1)

        if (h < NH - 1) sts_q_chunks(sQ, qc, t, sc);
    }

    // ---- writeout head means ----
    __syncthreads();
    const size_t AOFF = (size_t)B_SZ * GQ * HDIM * SLEN;       // 33554432
    const size_t LOFF = AOFF + (size_t)B_SZ * GQ * GQ * SLEN;  // 41943040
    const u64 cA = pk2(0.125f, 0.125f);
    const float lsc = 0.125f / L2E;                            // undo log2-domain
    const u64 cL = pk2(lsc, lsc);
    #pragma unroll
    for (int i = 0; i < 4; ++i) {
        int r  = t + NT * i;      // 0..1023
        int f  = r & 31;
        int gg = r >> 5;
        size_t o = ((size_t)(b * GQ + gg) * GQ + f) * SLEN + (size_t)s0;
        #pragma unroll
        for (int sp2 = 0; sp2 < 4; ++sp2) {
            int idx = (sp2 * 32 + f) * 32 + gg;
            *(u64*)(out + AOFF + o + 2 * sp2) = mul2(sA[idx], cA);
            *(u64*)(out + LOFF + o + 2 * sp2) = mul2(sL[idx], cL);
        }
    }
}

extern "C" void kernel_launch(void* const* d_in, const int* in_sizes, int n_in,
                              void* d_out, int out_size)
{
    const float* q = (const float*)d_in[0];
    const float* k = (const float*)d_in[1];
    const float* v = (const float*)d_in[2];
    float* out = (float*)d_out;

    cudaFuncSetAttribute(sdpa_group_kernel,
                         cudaFuncAttributeMaxDynamicSharedMemorySize, SM_BYTES);

    dim3 grid(SLEN / STILE, B_SZ);
    sdpa_group_kernel<<<grid, NT, SM_BYTES>>>(q, k, v, out);
}

// round 17
// speedup vs baseline: 1.2495x; 1.0975x over previous
#include <cuda_runtime.h>
#include <cstdint>

#define B_SZ  2
#define GQ    32
#define HDIM  128
#define NH    8
#define DK    16
#define SLEN  4096
#define STILE 8
#define NT    256

typedef unsigned long long u64;

// SMEM (u64 units), total 14336 u64 = 114688 B -> 2 CTAs/SM:
//  sQ   [0,2048)      [g:32][16B units]; unit (g,d,h) at g*32 + ((2d+h)^(g&7));
//                     prescaled by dk^-0.5*log2e
//  sK   [2048,4096)   [f:32][16B units]; unit (f,d,h) at f*32 + ((2d+h)^(f&7))
//    eX  = [0,4096)   u64[(sp*32+f)*32 + SWG(f,g)]  probs exchange (B2->B4)
//    xSt = [0,2048)   u64[(sp*16+d)*32 + g]         x staging (B4->B5)
//  sV   [4096,6144)   float[f*128 + d*8 + s]        (UNswizzled; dead after B4)
//  sL   [6144,10240)  u64[(sp*32+f)*32 + SWG(f,g)]  logits sums over h
//  sA   [10240,14336) same                          attn sums over h
//  SWG(f,g) = g ^ (2*(f&7))  (even xor: preserves (even g, g+1) pair adjacency)
#define SQ_U64   0
#define SK_U64   2048
#define SV_U64   4096
#define SL_U64   6144
#define SA_U64   10240
#define SM_U64_TOTAL 14336
#define SM_BYTES (SM_U64_TOTAL * 8)   // 114688

#define SWG(f, g) ((g) ^ (2 * ((f) & 7)))

// ---- packed f32x2 + misc helpers ----
__device__ __forceinline__ u64 pk2(float lo, float hi) {
    u64 r; asm("mov.b64 %0, {%1, %2};" : "=l"(r) : "f"(lo), "f"(hi)); return r;
}
__device__ __forceinline__ void up2(u64 v, float& lo, float& hi) {
    asm("mov.b64 {%0, %1}, %2;" : "=f"(lo), "=f"(hi) : "l"(v));
}
__device__ __forceinline__ u64 fma2(u64 a, u64 b, u64 c) {
    u64 d; asm("fma.rn.f32x2 %0, %1, %2, %3;" : "=l"(d) : "l"(a), "l"(b), "l"(c)); return d;
}
__device__ __forceinline__ u64 add2(u64 a, u64 b) {
    u64 d; asm("add.rn.f32x2 %0, %1, %2;" : "=l"(d) : "l"(a), "l"(b)); return d;
}
__device__ __forceinline__ u64 mul2(u64 a, u64 b) {
    u64 d; asm("mul.rn.f32x2 %0, %1, %2;" : "=l"(d) : "l"(a), "l"(b)); return d;
}
__device__ __forceinline__ float ex2a(float x) {
    float r; asm("ex2.approx.ftz.f32 %0, %1;" : "=f"(r) : "f"(x)); return r;
}
__device__ __forceinline__ float rcpa(float x) {
    float r; asm("rcp.approx.ftz.f32 %0, %1;" : "=f"(r) : "f"(x)); return r;
}
__device__ __forceinline__ u64 ex2a2(u64 v) {
    float a, b; up2(v, a, b);
    return pk2(ex2a(a), ex2a(b));
}
__device__ __forceinline__ u64 rcpa2(u64 v) {
    float a, b; up2(v, a, b);
    return pk2(rcpa(a), rcpa(b));
}
__device__ __forceinline__ void cp_async16(void* dst, const void* src) {
    unsigned sdst = (unsigned)__cvta_generic_to_shared(dst);
    asm volatile("cp.async.cg.shared.global [%0], [%1], 16;" :: "r"(sdst), "l"(src));
}
__device__ __forceinline__ void cp_commit() {
    asm volatile("cp.async.commit_group;" ::: "memory");
}
__device__ __forceinline__ void cp_wait0() {
    asm volatile("cp.async.wait_group 0;" ::: "memory");
}

// stage a 32x16x8-float tile: 1024 16B chunks, 4 per thread (NT=256).
// plain layout (V): unit c; swizzled layout (K): unit c ^ ((c>>5)&7)
__device__ __forceinline__ void stage_async(float* dst, const float* src0, int t) {
    #pragma unroll
    for (int i = 0; i < 4; ++i) {
        int c = t + NT * i;
        int r = c >> 1;                         // row = g*16 + d (or f*16 + d)
        const float* src = src0 + ((size_t)(r >> 4) * HDIM + (r & 15)) * SLEN + 4 * (c & 1);
        cp_async16(dst + 4 * c, src);
    }
}
__device__ __forceinline__ void stage_async_swK(float* dst, const float* src0, int t) {
    #pragma unroll
    for (int i = 0; i < 4; ++i) {
        int c = t + NT * i;                     // c = f*32 + d*2 + half
        int r = c >> 1;
        int u = c ^ ((c >> 5) & 7);             // xor (f&7) into (d*2+half)
        const float* src = src0 + ((size_t)(r >> 4) * HDIM + (r & 15)) * SLEN + 4 * (c & 1);
        cp_async16(dst + 4 * u, src);
    }
}

// Q: 1024 16B chunks by ALL 256 threads (4 each), coalesced-chunked LDG -> regs
__device__ __forceinline__ void load_q_chunks(ulonglong2* qc, const float* gq, int t) {
    #pragma unroll
    for (int i = 0; i < 4; ++i) {
        int c = t + NT * i;                     // c = (g*16+d)*2 + half
        int r = c >> 1;
        const float* src = gq + ((size_t)(r >> 4) * HDIM + (r & 15)) * SLEN + 4 * (c & 1);
        qc[i] = *(const ulonglong2*)src;
    }
}
// prescaled, swizzled STS: unit u = c ^ (g&7)
__device__ __forceinline__ void sts_q_chunks(u64* sQ, const ulonglong2* qc, int t, u64 sc) {
    #pragma unroll
    for (int i = 0; i < 4; ++i) {
        int c = t + NT * i;
        int gg = c >> 5;
        int u  = c ^ (gg & 7);
        ulonglong2 v;
        v.x = mul2(qc[i].x, sc);
        v.y = mul2(qc[i].y, sc);
        *(ulonglong2*)(sQ + 2 * u) = v;
    }
}

__global__ void __launch_bounds__(NT, 2)
sdpa_group_kernel(const float* __restrict__ q, const float* __restrict__ k,
                  const float* __restrict__ v, float* __restrict__ out)
{
    extern __shared__ u64 sm[];
    u64*   sQ   = sm + SQ_U64;
    u64*   sKu  = sm + SK_U64;
    u64*   eX   = sm + SQ_U64;     // overlay [0,4096), live B2->B4
    u64*   xSt  = sm + SQ_U64;     // overlay [0,2048), live B4->B5
    float* sV   = (float*)(sm + SV_U64);
    u64*   sL   = sm + SL_U64;
    u64*   sA   = sm + SA_U64;

    const int t    = threadIdx.x;
    const int g    = t & 31;
    const int warp = t >> 5;
    // logits roles: warp (sq, gq); lane (fo, gl)
    const int sq   = warp & 1;           // s-quad: spins (s-pairs) 2sq, 2sq+1
    const int gq   = warp >> 1;          // g-octet: g in [8gq, 8gq+8)
    const int fo   = g & 7;              // owns f in {fo, fo+8, fo+16, fo+24}
    const int gl   = g >> 3;             // owns g pair {8gq+2gl, 8gq+2gl+1}
    const int gA   = 8 * gq + 2 * gl;    // even
    const int xA   = gA & 7;             // = 2*gl
    const int xB   = xA + 1;
    // x-phase roles (R12/R16)
    const int sp   = warp & 3;
    const int fh   = warp >> 2;
    const int d0   = fh * 8;
    const int gb   = g & 7;
    const int db   = g >> 3;
    const int s0   = blockIdx.x * STILE;
    const int b    = blockIdx.y;

    const size_t base = (size_t)b * (GQ * HDIM) * SLEN + (size_t)s0;
    const float L2E = 1.4426950408889634f;
    const u64 sc = pk2(0.25f * L2E, 0.25f * L2E);        // dk^-0.5 * log2(e)

    // ---- prologue ----
    stage_async_swK((float*)sKu, k + base, t);
    stage_async(sV, v + base, t);
    cp_commit();
    ulonglong2 qc[4];
    load_q_chunks(qc, q + base, t);
    #pragma unroll 4
    for (int i = t; i < 8192; i += NT) sL[i] = 0ull;     // sL,sA contiguous
    sts_q_chunks(sQ, qc, t, sc);

    #pragma unroll 1
    for (int h = 0; h < NH; ++h) {
        cp_wait0();              // K(h), V(h) arrived
        __syncthreads();         // B1: tiles + Q(h) visible

        if (h < NH - 1)
            load_q_chunks(qc, q + base + (size_t)(h + 1) * DK * SLEN, t);

        // ---- logits (register-tiled 2g x 4f, log2 domain) ----
        // lgA*: g = gA, lgB*: g = gA+1; suffix 0/1 = spin 2sq / 2sq+1
        u64 lgA0[4], lgA1[4], lgB0[4], lgB1[4];
        {
            const u64* qbA = sQ + 2 * (gA * 32);
            const u64* qbB = sQ + 2 * ((gA + 1) * 32);
            const u64* kb0 = sKu + 2 * (fo * 32);        // f = fo + 8j rows
            #pragma unroll
            for (int d = 0; d < DK; ++d) {
                const int e2 = 2 * d + sq;
                ulonglong2 qa = *(const ulonglong2*)(qbA + 2 * (e2 ^ xA));
                ulonglong2 qb = *(const ulonglong2*)(qbB + 2 * (e2 ^ xB));
                const int ko = 2 * (e2 ^ fo);
                #pragma unroll
                for (int j = 0; j < 4; ++j) {
                    ulonglong2 kk = *(const ulonglong2*)(kb0 + j * 512 + ko);
                    if (d == 0) {
                        lgA0[j] = mul2(qa.x, kk.x); lgA1[j] = mul2(qa.y, kk.y);
                        lgB0[j] = mul2(qb.x, kk.x); lgB1[j] = mul2(qb.y, kk.y);
                    } else {
                        lgA0[j] = fma2(qa.x, kk.x, lgA0[j]);
                        lgA1[j] = fma2(qa.y, kk.y, lgA1[j]);
                        lgB0[j] = fma2(qb.x, kk.x, lgB0[j]);
                        lgB1[j] = fma2(qb.y, kk.y, lgB1[j]);
                    }
                }
            }
        }

        // ---- accumulate logits sums (paired, swizzled) + exp2 ----
        #pragma unroll
        for (int j = 0; j < 4; ++j) {
            const int f  = fo + 8 * j;
            const int gsw = SWG(f, gA);                  // even
            ulonglong2* p0 = (ulonglong2*)(sL + ((2 * sq)     * 32 + f) * 32 + gsw);
            ulonglong2* p1 = (ulonglong2*)(sL + ((2 * sq + 1) * 32 + f) * 32 + gsw);
            ulonglong2 c0 = *p0, c1 = *p1;
            c0.x = add2(c0.x, lgA0[j]); c0.y = add2(c0.y, lgB0[j]); *p0 = c0;
            c1.x = add2(c1.x, lgA1[j]); c1.y = add2(c1.y, lgB1[j]); *p1 = c1;
            lgA0[j] = ex2a2(lgA0[j]); lgA1[j] = ex2a2(lgA1[j]);
            lgB0[j] = ex2a2(lgB0[j]); lgB1[j] = ex2a2(lgB1[j]);
        }

        // ---- in-warp softmax sums: 4f per lane + shfl over fo (8 lanes) ----
        u64 rnA0, rnA1, rnB0, rnB1;
        {
            u64 pA0 = add2(add2(lgA0[0], lgA0[1]), add2(lgA0[2], lgA0[3]));
            u64 pA1 = add2(add2(lgA1[0], lgA1[1]), add2(lgA1[2], lgA1[3]));
            u64 pB0 = add2(add2(lgB0[0], lgB0[1]), add2(lgB0[2], lgB0[3]));
            u64 pB1 = add2(add2(lgB1[0], lgB1[1]), add2(lgB1[2], lgB1[3]));
            #pragma unroll
            for (int m = 1; m < 8; m <<= 1) {
                pA0 = add2(pA0, __shfl_xor_sync(0xffffffffu, pA0, m));
                pA1 = add2(pA1, __shfl_xor_sync(0xffffffffu, pA1, m));
                pB0 = add2(pB0, __shfl_xor_sync(0xffffffffu, pB0, m));
                pB1 = add2(pB1, __shfl_xor_sync(0xffffffffu, pB1, m));
            }
            rnA0 = rcpa2(pA0); rnA1 = rcpa2(pA1);
            rnB0 = rcpa2(pB0); rnB1 = rcpa2(pB1);
        }
        // normalize in registers (rn known before B2)
        #pragma unroll
        for (int j = 0; j < 4; ++j) {
            lgA0[j] = mul2(lgA0[j], rnA0); lgA1[j] = mul2(lgA1[j], rnA1);
            lgB0[j] = mul2(lgB0[j], rnB0); lgB1[j] = mul2(lgB1[j], rnB1);
        }

        __syncthreads();         // B2: all sQ/sK reads done -> eX overlay writable

        // ---- accumulate attn sums + post probs to eX (paired, swizzled) ----
        #pragma unroll
        for (int j = 0; j < 4; ++j) {
            const int f  = fo + 8 * j;
            const int gsw = SWG(f, gA);
            const int i0 = ((2 * sq)     * 32 + f) * 32 + gsw;
            const int i1 = ((2 * sq + 1) * 32 + f) * 32 + gsw;
            ulonglong2* a0 = (ulonglong2*)(sA + i0);
            ulonglong2* a1 = (ulonglong2*)(sA + i1);
            ulonglong2 c0 = *a0, c1 = *a1;
            c0.x = add2(c0.x, lgA0[j]); c0.y = add2(c0.y, lgB0[j]); *a0 = c0;
            c1.x = add2(c1.x, lgA1[j]); c1.y = add2(c1.y, lgB1[j]); *a1 = c1;
            ulonglong2 e0, e1;
            e0.x = lgA0[j]; e0.y = lgB0[j];
            e1.x = lgA1[j]; e1.y = lgB1[j];
            *(ulonglong2*)(eX + i0) = e0;
            *(ulonglong2*)(eX + i1) = e1;
        }
        __syncthreads();         // B3: probs posted

        // ---- x phase (register-tiled, conflict-free; R16):
        //      lane owns d in {d0+db, d0+db+4}, g in {2gb,2gb+1,2gb+16,2gb+17} ----
        u64 xa[4], xb[4];
        {
            const float* vf0 = sV + (d0 + db) * 8 + 2 * sp;      // f stride 128 fl
            {
                const u64* er = eX + (sp * 32) * 32;             // f = 0, E = 0
                ulonglong2 pA = *(const ulonglong2*)(er + 2 * gb);
                ulonglong2 pB = *(const ulonglong2*)(er + 2 * gb + 16);
                u64 va = *(const u64*)(vf0);
                u64 vb = *(const u64*)(vf0 + 32);
                xa[0] = mul2(pA.x, va); xa[1] = mul2(pA.y, va);
                xa[2] = mul2(pB.x, va); xa[3] = mul2(pB.y, va);
                xb[0] = mul2(pA.x, vb); xb[1] = mul2(pA.y, vb);
                xb[2] = mul2(pB.x, vb); xb[3] = mul2(pB.y, vb);
            }
            #pragma unroll
            for (int f = 1; f < GQ; ++f) {
                const int gsw = (2 * gb) ^ (2 * (f & 7));
                const u64* er = eX + (sp * 32 + f) * 32;
                const float* vf = vf0 + f * 128;
                ulonglong2 pA = *(const ulonglong2*)(er + gsw);
                ulonglong2 pB = *(const ulonglong2*)(er + gsw + 16);
                u64 va = *(const u64*)(vf);
                u64 vb = *(const u64*)(vf + 32);
                xa[0] = fma2(pA.x, va, xa[0]); xa[1] = fma2(pA.y, va, xa[1]);
                xa[2] = fma2(pB.x, va, xa[2]); xa[3] = fma2(pB.y, va, xa[3]);
                xb[0] = fma2(pA.x, vb, xb[0]); xb[1] = fma2(pA.y, vb, xb[1]);
                xb[2] = fma2(pB.x, vb, xb[2]); xb[3] = fma2(pB.y, vb, xb[3]);
            }
        }
        __syncthreads();         // B4: x-FMAs done everywhere (eX, sV, sK dead)

        // prefetch K(h+1), V(h+1)
        if (h < NH - 1) {
            stage_async_swK((float*)sKu, k + base + (size_t)(h + 1) * DK * SLEN, t);
            stage_async(sV, v + base + (size_t)(h + 1) * DK * SLEN, t);
            cp_commit();
        }

        // ---- stage x into xSt [(sp*16+d)*32+g] via STS.128 ----
        {
            u64* ra = xSt + (sp * 16 + d0 + db)     * 32 + 2 * gb;
            u64* rb = xSt + (sp * 16 + d0 + db + 4) * 32 + 2 * gb;
            ulonglong2 w;
            w.x = xa[0]; w.y = xa[1]; *(ulonglong2*)ra = w;
            w.x = xa[2]; w.y = xa[3]; *(ulonglong2*)(ra + 16) = w;
            w.x = xb[0]; w.y = xb[1]; *(ulonglong2*)rb = w;
            w.x = xb[2]; w.y = xb[3]; *(ulonglong2*)(rb + 16) = w;
        }
        __syncthreads();         // B4.5: x staged

        // ---- cooperative coalesced STG: row (g,d) = 32B, 2 lanes per row ----
        #pragma unroll
        for (int i = 0; i < 4; ++i) {
            int u    = t + NT * i;        // 0..1023 units of 16B
            int r    = u >> 1;
            int half = u & 1;
            int dd   = r >> 5;
            int g2   = r & 31;
            u64 lo = xSt[((2 * half)     * 16 + dd) * 32 + g2];
            u64 hi = xSt[((2 * half + 1) * 16 + dd) * 32 + g2];
            float* dst = out + ((size_t)((b * GQ + g2) * HDIM) + (size_t)h * DK + dd) * SLEN
                             + (size_t)s0 + 4 * half;
            ulonglong2 val; val.x = lo; val.y = hi;
            *(ulonglong2*)dst = val;
        }
        __syncthreads();         // B5: staging reads done -> region free for Q(h+1)

        if (h < NH - 1) sts_q_chunks(sQ, qc, t, sc);
    }

    // ---- writeout head means ----
    __syncthreads();
    const size_t AOFF = (size_t)B_SZ * GQ * HDIM * SLEN;       // 33554432
    const size_t LOFF = AOFF + (size_t)B_SZ * GQ * GQ * SLEN;  // 41943040
    const u64 cA = pk2(0.125f, 0.125f);
    const float lsc = 0.125f / L2E;                            // undo log2-domain
    const u64 cL = pk2(lsc, lsc);
    #pragma unroll
    for (int i = 0; i < 4; ++i) {
        int r  = t + NT * i;      // 0..1023
        int f  = r & 31;
        int gg = r >> 5;
        size_t o = ((size_t)(b * GQ + gg) * GQ + f) * SLEN + (size_t)s0;
        #pragma unroll
        for (int sp2 = 0; sp2 < 4; ++sp2) {
            int idx = (sp2 * 32 + f) * 32 + SWG(f, gg);
            *(u64*)(out + AOFF + o + 2 * sp2) = mul2(sA[idx], cA);
            *(u64*)(out + LOFF + o + 2 * sp2) = mul2(sL[idx], cL);
        }
    }
}

extern "C" void kernel_launch(void* const* d_in, const int* in_sizes, int n_in,
                              void* d_out, int out_size)
{
    const float* q = (const float*)d_in[0];
    const float* k = (const float*)d_in[1];
    const float* v = (const float*)d_in[2];
    float* out = (float*)d_out;

    cudaFuncSetAttribute(sdpa_group_kernel,
                         cudaFuncAttributeMaxDynamicSharedMemorySize, SM_BYTES);

    dim3 grid(SLEN / STILE, B_SZ);
    sdpa_group_kernel<<<grid, NT, SM_BYTES>>>(q, k, v, out);
}